// round 15
// baseline (speedup 1.0000x reference)
#include <cuda_runtime.h>
#include <cuda_bf16.h>
#include <math.h>
#include <cstdint>

// Problem constants
#define B_  4096
#define F_  26
#define E_  64
#define D_  1664          // F_*E_
#define NV4 (D_ / 4)
#define N1  1024
#define N2  512
#define N3  256

// Scratch (no cudaMalloc allowed)
__device__ __nv_bfloat16 g_x0b[B_ * D_];
__device__ float        g_qrow[B_ * 4];     // per-row dots q0..q3
__device__ float        g_tconst[3];
__device__ __nv_bfloat16 g_h1b[B_ * N1];
__device__ __nv_bfloat16 g_h2b[B_ * N2];
__device__ __nv_bfloat16 g_h3b[B_ * N3];
__device__ __nv_bfloat16 g_w1t[N1 * D_];
__device__ __nv_bfloat16 g_w2t[N2 * N1];
__device__ __nv_bfloat16 g_w3t[N3 * N2];

__device__ __forceinline__ uint32_t smem_u32(const void* p) {
    return (uint32_t)__cvta_generic_to_shared(p);
}
#define CP16(dst, src) \
    asm volatile("cp.async.ca.shared.global [%0], [%1], 16;\n" :: "r"(dst), "l"(src))
#define CP_COMMIT() asm volatile("cp.async.commit_group;\n")

__device__ __forceinline__ void ldsm_x4(uint32_t& r0, uint32_t& r1,
                                        uint32_t& r2, uint32_t& r3, uint32_t a) {
    asm volatile("ldmatrix.sync.aligned.m8n8.x4.shared.b16 {%0,%1,%2,%3}, [%4];\n"
                 : "=r"(r0), "=r"(r1), "=r"(r2), "=r"(r3) : "r"(a));
}

// ---------------------------------------------------------------------------
// k_front: ONE launch doing (a) fused gather + cross dots (blocks 0..1023,
// ordered first -> starts immediately, on GEMM1's critical path), and
// (b) weight transposes + cross constants (remaining blocks).
// ---------------------------------------------------------------------------
#define RPB 4
#define GB_ (B_ / RPB)                          // 1024 gather blocks
#define T1_TILES ((N1/32)*(D_/32))              // 1664
#define T2_TILES ((N2/32)*(N1/32))              // 512
#define T3_TILES ((N3/32)*(N2/32))              // 128
#define FRONT_BLOCKS (GB_ + T1_TILES + T2_TILES + T3_TILES + 1)

__global__ __launch_bounds__(256) void k_front(
    const int* __restrict__ ids,
    const float* __restrict__ emb,
    const float* __restrict__ cross_w,
    const float* __restrict__ cross_b,
    const float* __restrict__ out_w,
    const float* __restrict__ w1, const float* __restrict__ w2,
    const float* __restrict__ w3,
    __nv_bfloat16* __restrict__ w1t, __nv_bfloat16* __restrict__ w2t,
    __nv_bfloat16* __restrict__ w3t)
{
    const int bid = blockIdx.x;
    const int tid = threadIdx.x;

    if (bid < GB_) {
        __shared__ int sid[RPB][F_];
        __shared__ float sred[RPB][4][8];
        const int b0 = bid * RPB;

        if (tid < RPB * F_) {
            int r = tid / F_, f = tid % F_;
            sid[r][f] = ids[(b0 + r) * F_ + f];
        }
        __syncthreads();

        float q[RPB][4];
#pragma unroll
        for (int r = 0; r < RPB; r++)
#pragma unroll
            for (int c = 0; c < 4; c++) q[r][c] = 0.f;

        for (int v4 = tid; v4 < NV4; v4 += 256) {
            int f = v4 >> 4;
            int e4 = (v4 & 15) << 2;
            int d = v4 << 2;

            float4 w0 = *(const float4*)&cross_w[d];
            float4 wa = *(const float4*)&cross_w[D_ + d];
            float4 wb = *(const float4*)&cross_w[2 * D_ + d];
            float4 wo = *(const float4*)&out_w[d];

#pragma unroll
            for (int r = 0; r < RPB; r++) {
                int row = sid[r][f];
                float4 v = *(const float4*)&emb[(size_t)row * E_ + e4];
                q[r][0] += v.x * w0.x + v.y * w0.y + v.z * w0.z + v.w * w0.w;
                q[r][1] += v.x * wa.x + v.y * wa.y + v.z * wa.z + v.w * wa.w;
                q[r][2] += v.x * wb.x + v.y * wb.y + v.z * wb.z + v.w * wb.w;
                q[r][3] += v.x * wo.x + v.y * wo.y + v.z * wo.z + v.w * wo.w;

                __nv_bfloat162 p0 = __floats2bfloat162_rn(v.x, v.y);
                __nv_bfloat162 p1 = __floats2bfloat162_rn(v.z, v.w);
                uint2 pk;
                pk.x = *(uint32_t*)&p0;
                pk.y = *(uint32_t*)&p1;
                *(uint2*)&g_x0b[(size_t)(b0 + r) * D_ + d] = pk;
            }
        }

#pragma unroll
        for (int r = 0; r < RPB; r++)
#pragma unroll
            for (int c = 0; c < 4; c++)
#pragma unroll
                for (int o = 16; o > 0; o >>= 1)
                    q[r][c] += __shfl_xor_sync(0xffffffffu, q[r][c], o);

        int w = tid >> 5, l = tid & 31;
        if (l == 0)
#pragma unroll
            for (int r = 0; r < RPB; r++)
#pragma unroll
                for (int c = 0; c < 4; c++) sred[r][c][w] = q[r][c];
        __syncthreads();
        if (tid < RPB * 4) {
            int r = tid >> 2, c = tid & 3;
            float v = 0.f;
#pragma unroll
            for (int j = 0; j < 8; j++) v += sred[r][c][j];
            g_qrow[(b0 + r) * 4 + c] = v;
        }
        return;
    }

    const int pb = bid - GB_;
    if (pb == T1_TILES + T2_TILES + T3_TILES) {
        __shared__ float sred[3][8];
        float a1 = 0.f, a2 = 0.f, a3 = 0.f;
        for (int d = tid; d < D_; d += 256) {
            float c0 = cross_b[d];
            float c01 = c0 + cross_b[D_ + d];
            float c012 = c01 + cross_b[2 * D_ + d];
            a1 += c0   * cross_w[D_ + d];
            a2 += c01  * cross_w[2 * D_ + d];
            a3 += c012 * out_w[d];
        }
#pragma unroll
        for (int o = 16; o > 0; o >>= 1) {
            a1 += __shfl_xor_sync(0xffffffffu, a1, o);
            a2 += __shfl_xor_sync(0xffffffffu, a2, o);
            a3 += __shfl_xor_sync(0xffffffffu, a3, o);
        }
        int w = tid >> 5, l = tid & 31;
        if (l == 0) { sred[0][w] = a1; sred[1][w] = a2; sred[2][w] = a3; }
        __syncthreads();
        if (tid < 3) {
            float v = 0.f;
#pragma unroll
            for (int j = 0; j < 8; j++) v += sred[tid][j];
            g_tconst[tid] = v;
        }
        return;
    }

    const float* W; __nv_bfloat16* Wt; int K, N, tile;
    if (pb < T1_TILES)                 { W = w1; Wt = w1t; K = D_; N = N1; tile = pb; }
    else if (pb < T1_TILES + T2_TILES) { W = w2; Wt = w2t; K = N1; N = N2; tile = pb - T1_TILES; }
    else                               { W = w3; Wt = w3t; K = N2; N = N3; tile = pb - T1_TILES - T2_TILES; }

    __shared__ float s[32][33];
    const int tilesN = N / 32;
    const int n0 = (tile % tilesN) * 32, k0 = (tile / tilesN) * 32;
    const int tx = tid & 31, ty = tid >> 5;
#pragma unroll
    for (int i = 0; i < 32; i += 8)
        s[ty + i][tx] = W[(size_t)(k0 + ty + i) * N + n0 + tx];
    __syncthreads();
#pragma unroll
    for (int i = 0; i < 32; i += 8)
        Wt[(size_t)(n0 + ty + i) * K + k0 + tx] = __float2bfloat16(s[tx][ty + i]);
}

// ---------------------------------------------------------------------------
// bf16 tensor-core GEMM + bias + relu.
// S-stage cp.async circular pipeline, ONE __syncthreads per BK=32 slab,
// ldmatrix.x4 fragment loads. BM=WM*MT*16, BN=WN*NT*8, THREADS=WM*WN*32.
// Dynamic smem: S*(BM+BN)*40*2 bytes.
// ---------------------------------------------------------------------------
template<int WM, int WN, int MT, int NT, int S>
__global__ __launch_bounds__(WM * WN * 32) void k_gemm_bf16(
    const __nv_bfloat16* __restrict__ A,   // [M][K]
    const __nv_bfloat16* __restrict__ Bt,  // [N][K]
    const float* __restrict__ bias,        // [N]
    __nv_bfloat16* __restrict__ C,         // [M][N]
    int M, int N, int K)
{
    constexpr int BM = WM * MT * 16;
    constexpr int BN = WN * NT * 8;
    constexpr int T  = WM * WN * 32;
    constexpr int RG = T / 4;              // rows covered per loader pass
    static_assert(NT % 2 == 0, "NT must be even for paired ldmatrix");
    static_assert(BM % 64 == 0 && BN % 64 == 0, "64-row granularity");
    static_assert(S >= 3 && S <= 4, "pipeline depth 3..4");

    extern __shared__ __align__(16) unsigned char smem_raw[];
    __nv_bfloat16 (*As)[40] = reinterpret_cast<__nv_bfloat16 (*)[40]>(smem_raw);
    __nv_bfloat16 (*Bs)[40] =
        reinterpret_cast<__nv_bfloat16 (*)[40]>(smem_raw + (size_t)S * BM * 40 * 2);

    const int tid  = threadIdx.x;
    const int warp = tid >> 5, lane = tid & 31;
    const int g = lane >> 2, t = lane & 3;
    const int wm = (warp % WM) * (MT * 16);
    const int wn = (warp / WM) * (NT * 8);
    const int bm0 = blockIdx.y * BM;
    const int bn0 = blockIdx.x * BN;

    const int a_row = wm + (lane & 15);
    const int a_col = (lane >> 4) << 3;
    const int b_row = wn + (lane & 7) + ((lane >> 4) << 3);
    const int b_col = ((lane >> 3) & 1) << 3;

    float acc[MT][NT][4];
#pragma unroll
    for (int i = 0; i < MT; i++)
#pragma unroll
        for (int j = 0; j < NT; j++)
#pragma unroll
            for (int c = 0; c < 4; c++) acc[i][j][c] = 0.0f;

    const int r_  = tid >> 2;          // 0..RG-1
    const int kp_ = (tid & 3) * 8;

    auto load_stage = [&](int s, int k0) {
#pragma unroll
        for (int r = r_; r < BM; r += RG)
            CP16(smem_u32(&As[s * BM + r][kp_]),
                 &A[(size_t)(bm0 + r) * K + k0 + kp_]);
#pragma unroll
        for (int r = r_; r < BN; r += RG)
            CP16(smem_u32(&Bs[s * BN + r][kp_]),
                 &Bt[(size_t)(bn0 + r) * K + k0 + kp_]);
        CP_COMMIT();
    };

    const int niter = K >> 5;
#pragma unroll
    for (int s = 0; s < S - 1; s++)
        if (s < niter) load_stage(s, s << 5);

    for (int it = 0; it < niter; it++) {
        const int buf = it % S;
        int allow = niter - it - 1;
        if (allow > S - 2) allow = S - 2;
        if (allow >= 2)      asm volatile("cp.async.wait_group 2;\n");
        else if (allow == 1) asm volatile("cp.async.wait_group 1;\n");
        else                 asm volatile("cp.async.wait_group 0;\n");
        __syncthreads();

        if (it + S - 1 < niter) load_stage((it + S - 1) % S, (it + S - 1) << 5);

#pragma unroll
        for (int ks = 0; ks < 32; ks += 16) {
            uint32_t af[MT][4], bf[NT][2];
#pragma unroll
            for (int mt = 0; mt < MT; mt++)
                ldsm_x4(af[mt][0], af[mt][1], af[mt][2], af[mt][3],
                        smem_u32(&As[buf * BM + a_row + mt * 16][a_col + ks]));
#pragma unroll
            for (int p = 0; p < NT / 2; p++)
                ldsm_x4(bf[2 * p][0], bf[2 * p][1], bf[2 * p + 1][0], bf[2 * p + 1][1],
                        smem_u32(&Bs[buf * BN + b_row + p * 16][b_col + ks]));
#pragma unroll
            for (int mt = 0; mt < MT; mt++)
#pragma unroll
                for (int nt = 0; nt < NT; nt++) {
                    asm volatile(
                        "mma.sync.aligned.m16n8k16.row.col.f32.bf16.bf16.f32 "
                        "{%0,%1,%2,%3}, {%4,%5,%6,%7}, {%8,%9}, {%0,%1,%2,%3};\n"
                        : "+f"(acc[mt][nt][0]), "+f"(acc[mt][nt][1]),
                          "+f"(acc[mt][nt][2]), "+f"(acc[mt][nt][3])
                        : "r"(af[mt][0]), "r"(af[mt][1]), "r"(af[mt][2]), "r"(af[mt][3]),
                          "r"(bf[nt][0]), "r"(bf[nt][1]));
                }
        }
    }

#pragma unroll
    for (int mt = 0; mt < MT; mt++) {
        int row0 = bm0 + wm + mt * 16 + g;
#pragma unroll
        for (int nt = 0; nt < NT; nt++) {
            int col = bn0 + wn + nt * 8 + 2 * t;
            float b0v = bias[col], b1v = bias[col + 1];
            float v00 = fmaxf(acc[mt][nt][0] + b0v, 0.0f);
            float v01 = fmaxf(acc[mt][nt][1] + b1v, 0.0f);
            float v10 = fmaxf(acc[mt][nt][2] + b0v, 0.0f);
            float v11 = fmaxf(acc[mt][nt][3] + b1v, 0.0f);
            __nv_bfloat162 p0 = __floats2bfloat162_rn(v00, v01);
            __nv_bfloat162 p1 = __floats2bfloat162_rn(v10, v11);
            *(__nv_bfloat162*)&C[(size_t)row0 * N + col]       = p0;
            *(__nv_bfloat162*)&C[(size_t)(row0 + 8) * N + col] = p1;
        }
    }
}

// ---------------------------------------------------------------------------
// Head: cross recurrence + h3 dot + sigmoid. One warp per row, 8 rows/block.
// ---------------------------------------------------------------------------
__global__ __launch_bounds__(256) void k_head(
    const __nv_bfloat16* __restrict__ h3,
    const float* __restrict__ out_w,
    const float* __restrict__ out_b,
    float* __restrict__ out)
{
    const int b = blockIdx.x * 8 + (threadIdx.x >> 5);
    const int l = threadIdx.x & 31;
    float p = 0.0f;
#pragma unroll
    for (int j = 0; j < N3 / 32; j++) {
        int idx = l + j * 32;
        p += __bfloat162float(h3[b * N3 + idx]) * out_w[D_ + idx];
    }
#pragma unroll
    for (int o = 16; o > 0; o >>= 1) p += __shfl_xor_sync(0xffffffffu, p, o);
    if (l == 0) {
        float4 rr = *(const float4*)&g_qrow[b * 4];
        float t1 = g_tconst[0], t2 = g_tconst[1], u = g_tconst[2];
        float a1 = 1.0f + rr.x;
        float s1 = a1 * rr.y + t1;
        float a2 = a1 + s1;
        float s2 = a2 * rr.z + t2;
        float a3 = a2 + s2;
        float xdot = a3 * rr.w + u;
        float logit = xdot + p + out_b[0];
        out[b] = 1.0f / (1.0f + expf(-logit));
    }
}

// ---------------------------------------------------------------------------
extern "C" void kernel_launch(void* const* d_in, const int* in_sizes, int n_in,
                              void* d_out, int out_size)
{
    const int*   ids     = (const int*)  d_in[0];
    const float* emb     = (const float*)d_in[1];
    const float* cross_w = (const float*)d_in[2];
    const float* cross_b = (const float*)d_in[3];
    const float* w1      = (const float*)d_in[4];
    const float* b1      = (const float*)d_in[5];
    const float* w2      = (const float*)d_in[6];
    const float* b2      = (const float*)d_in[7];
    const float* w3      = (const float*)d_in[8];
    const float* b3      = (const float*)d_in[9];
    const float* out_w   = (const float*)d_in[10];
    const float* out_b   = (const float*)d_in[11];
    float* out = (float*)d_out;

    __nv_bfloat16 *x0b, *h1b, *h2b, *h3b, *w1t, *w2t, *w3t;
    cudaGetSymbolAddress((void**)&x0b, g_x0b);
    cudaGetSymbolAddress((void**)&h1b, g_h1b);
    cudaGetSymbolAddress((void**)&h2b, g_h2b);
    cudaGetSymbolAddress((void**)&h3b, g_h3b);
    cudaGetSymbolAddress((void**)&w1t, g_w1t);
    cudaGetSymbolAddress((void**)&w2t, g_w2t);
    cudaGetSymbolAddress((void**)&w3t, g_w3t);

    // dynamic smem: S * (BM+BN) * 40 * 2 bytes
    const int smem1 = 3 * (128 + 128) * 40 * 2;   // 61440 (opt-in)
    const int smem2 = 4 * (128 +  64) * 40 * 2;   // 61440 (opt-in)
    const int smem3 = 4 * ( 64 +  64) * 40 * 2;   // 40960
    cudaFuncSetAttribute((const void*)k_gemm_bf16<4, 4, 2, 4, 3>,
                         cudaFuncAttributeMaxDynamicSharedMemorySize, smem1);
    cudaFuncSetAttribute((const void*)k_gemm_bf16<8, 2, 1, 4, 4>,
                         cudaFuncAttributeMaxDynamicSharedMemorySize, smem2);

    // 0+1) gather + all prep fused into ONE launch (gather blocks first)
    k_front<<<FRONT_BLOCKS, 256>>>(ids, emb, cross_w, cross_b, out_w,
                                   w1, w2, w3, w1t, w2t, w3t);

    // 2) deep tower — same tiles/grids as 103.1us baseline, 16 warps per CTA
    k_gemm_bf16<4, 4, 2, 4, 3><<<dim3(N1 / 128, B_ / 128), 512, smem1>>>(x0b, w1t, b1, h1b, B_, N1, D_);
    k_gemm_bf16<8, 2, 1, 4, 4><<<dim3(N2 /  64, B_ / 128), 512, smem2>>>(h1b, w2t, b2, h2b, B_, N2, N1);
    k_gemm_bf16<4, 4, 1, 2, 4><<<dim3(N3 /  64, B_ /  64), 512, smem3>>>(h2b, w3t, b3, h3b, B_, N3, N2);

    // 3) head (includes cross recurrence)
    k_head<<<B_ / 8, 256>>>(h3b, out_w, out_b, out);
}

// round 16
// speedup vs baseline: 1.1869x; 1.1869x over previous
#include <cuda_runtime.h>
#include <cuda_bf16.h>
#include <math.h>
#include <cstdint>

// Problem constants
#define B_  4096
#define F_  26
#define E_  64
#define D_  1664          // F_*E_
#define NV4 (D_ / 4)
#define N1  1024
#define N2  512
#define N3  256

// Scratch (no cudaMalloc allowed)
__device__ __nv_bfloat16 g_x0b[B_ * D_];
__device__ float        g_qrow[B_ * 4];     // per-row dots q0..q3
__device__ float        g_tconst[3];
__device__ __nv_bfloat16 g_h1b[B_ * N1];
__device__ __nv_bfloat16 g_h2b[B_ * N2];
__device__ __nv_bfloat16 g_h3b[B_ * N3];
__device__ __nv_bfloat16 g_w1t[N1 * D_];
__device__ __nv_bfloat16 g_w2t[N2 * N1];
__device__ __nv_bfloat16 g_w3t[N3 * N2];

__device__ __forceinline__ uint32_t smem_u32(const void* p) {
    return (uint32_t)__cvta_generic_to_shared(p);
}
#define CP16(dst, src) \
    asm volatile("cp.async.ca.shared.global [%0], [%1], 16;\n" :: "r"(dst), "l"(src))
#define CP_COMMIT() asm volatile("cp.async.commit_group;\n")

__device__ __forceinline__ void ldsm_x4(uint32_t& r0, uint32_t& r1,
                                        uint32_t& r2, uint32_t& r3, uint32_t a) {
    asm volatile("ldmatrix.sync.aligned.m8n8.x4.shared.b16 {%0,%1,%2,%3}, [%4];\n"
                 : "=r"(r0), "=r"(r1), "=r"(r2), "=r"(r3) : "r"(a));
}

// ---------------------------------------------------------------------------
// k_front: ONE launch: gather + cross dots (blocks 0..1023, first) and
// weight transposes + cross constants (remaining blocks).
// ---------------------------------------------------------------------------
#define RPB 4
#define GB_ (B_ / RPB)                          // 1024 gather blocks
#define T1_TILES ((N1/32)*(D_/32))              // 1664
#define T2_TILES ((N2/32)*(N1/32))              // 512
#define T3_TILES ((N3/32)*(N2/32))              // 128
#define FRONT_BLOCKS (GB_ + T1_TILES + T2_TILES + T3_TILES + 1)

__global__ __launch_bounds__(256) void k_front(
    const int* __restrict__ ids,
    const float* __restrict__ emb,
    const float* __restrict__ cross_w,
    const float* __restrict__ cross_b,
    const float* __restrict__ out_w,
    const float* __restrict__ w1, const float* __restrict__ w2,
    const float* __restrict__ w3,
    __nv_bfloat16* __restrict__ w1t, __nv_bfloat16* __restrict__ w2t,
    __nv_bfloat16* __restrict__ w3t)
{
    const int bid = blockIdx.x;
    const int tid = threadIdx.x;

    if (bid < GB_) {
        __shared__ int sid[RPB][F_];
        __shared__ float sred[RPB][4][8];
        const int b0 = bid * RPB;

        if (tid < RPB * F_) {
            int r = tid / F_, f = tid % F_;
            sid[r][f] = ids[(b0 + r) * F_ + f];
        }
        __syncthreads();

        float q[RPB][4];
#pragma unroll
        for (int r = 0; r < RPB; r++)
#pragma unroll
            for (int c = 0; c < 4; c++) q[r][c] = 0.f;

        for (int v4 = tid; v4 < NV4; v4 += 256) {
            int f = v4 >> 4;
            int e4 = (v4 & 15) << 2;
            int d = v4 << 2;

            float4 w0 = *(const float4*)&cross_w[d];
            float4 wa = *(const float4*)&cross_w[D_ + d];
            float4 wb = *(const float4*)&cross_w[2 * D_ + d];
            float4 wo = *(const float4*)&out_w[d];

#pragma unroll
            for (int r = 0; r < RPB; r++) {
                int row = sid[r][f];
                float4 v = *(const float4*)&emb[(size_t)row * E_ + e4];
                q[r][0] += v.x * w0.x + v.y * w0.y + v.z * w0.z + v.w * w0.w;
                q[r][1] += v.x * wa.x + v.y * wa.y + v.z * wa.z + v.w * wa.w;
                q[r][2] += v.x * wb.x + v.y * wb.y + v.z * wb.z + v.w * wb.w;
                q[r][3] += v.x * wo.x + v.y * wo.y + v.z * wo.z + v.w * wo.w;

                __nv_bfloat162 p0 = __floats2bfloat162_rn(v.x, v.y);
                __nv_bfloat162 p1 = __floats2bfloat162_rn(v.z, v.w);
                uint2 pk;
                pk.x = *(uint32_t*)&p0;
                pk.y = *(uint32_t*)&p1;
                *(uint2*)&g_x0b[(size_t)(b0 + r) * D_ + d] = pk;
            }
        }

#pragma unroll
        for (int r = 0; r < RPB; r++)
#pragma unroll
            for (int c = 0; c < 4; c++)
#pragma unroll
                for (int o = 16; o > 0; o >>= 1)
                    q[r][c] += __shfl_xor_sync(0xffffffffu, q[r][c], o);

        int w = tid >> 5, l = tid & 31;
        if (l == 0)
#pragma unroll
            for (int r = 0; r < RPB; r++)
#pragma unroll
                for (int c = 0; c < 4; c++) sred[r][c][w] = q[r][c];
        __syncthreads();
        if (tid < RPB * 4) {
            int r = tid >> 2, c = tid & 3;
            float v = 0.f;
#pragma unroll
            for (int j = 0; j < 8; j++) v += sred[r][c][j];
            g_qrow[(b0 + r) * 4 + c] = v;
        }
        return;
    }

    const int pb = bid - GB_;
    if (pb == T1_TILES + T2_TILES + T3_TILES) {
        __shared__ float sred[3][8];
        float a1 = 0.f, a2 = 0.f, a3 = 0.f;
        for (int d = tid; d < D_; d += 256) {
            float c0 = cross_b[d];
            float c01 = c0 + cross_b[D_ + d];
            float c012 = c01 + cross_b[2 * D_ + d];
            a1 += c0   * cross_w[D_ + d];
            a2 += c01  * cross_w[2 * D_ + d];
            a3 += c012 * out_w[d];
        }
#pragma unroll
        for (int o = 16; o > 0; o >>= 1) {
            a1 += __shfl_xor_sync(0xffffffffu, a1, o);
            a2 += __shfl_xor_sync(0xffffffffu, a2, o);
            a3 += __shfl_xor_sync(0xffffffffu, a3, o);
        }
        int w = tid >> 5, l = tid & 31;
        if (l == 0) { sred[0][w] = a1; sred[1][w] = a2; sred[2][w] = a3; }
        __syncthreads();
        if (tid < 3) {
            float v = 0.f;
#pragma unroll
            for (int j = 0; j < 8; j++) v += sred[tid][j];
            g_tconst[tid] = v;
        }
        return;
    }

    const float* W; __nv_bfloat16* Wt; int K, N, tile;
    if (pb < T1_TILES)                 { W = w1; Wt = w1t; K = D_; N = N1; tile = pb; }
    else if (pb < T1_TILES + T2_TILES) { W = w2; Wt = w2t; K = N1; N = N2; tile = pb - T1_TILES; }
    else                               { W = w3; Wt = w3t; K = N2; N = N3; tile = pb - T1_TILES - T2_TILES; }

    __shared__ float s[32][33];
    const int tilesN = N / 32;
    const int n0 = (tile % tilesN) * 32, k0 = (tile / tilesN) * 32;
    const int tx = tid & 31, ty = tid >> 5;
#pragma unroll
    for (int i = 0; i < 32; i += 8)
        s[ty + i][tx] = W[(size_t)(k0 + ty + i) * N + n0 + tx];
    __syncthreads();
#pragma unroll
    for (int i = 0; i < 32; i += 8)
        Wt[(size_t)(n0 + ty + i) * K + k0 + tx] = __float2bfloat16(s[tx][ty + i]);
}

// ---------------------------------------------------------------------------
// bf16 tensor-core GEMM + bias + relu. BK=64 slabs (stride-72 smem rows,
// conflict-free for ldmatrix), 3-stage cp.async pipeline, ONE __syncthreads
// per slab. BM=WM*MT*16, BN=WN*NT*8, 256 threads.
// Dynamic smem: 3*(BM+BN)*72*2 bytes.
// ---------------------------------------------------------------------------
template<int WM, int WN, int MT, int NT>
__global__ __launch_bounds__(256) void k_gemm_bf16(
    const __nv_bfloat16* __restrict__ A,   // [M][K]
    const __nv_bfloat16* __restrict__ Bt,  // [N][K]
    const float* __restrict__ bias,        // [N]
    __nv_bfloat16* __restrict__ C,         // [M][N]
    int M, int N, int K)
{
    constexpr int BM = WM * MT * 16;
    constexpr int BN = WN * NT * 8;
    constexpr int S  = 3;
    static_assert(NT % 2 == 0, "NT must be even for paired ldmatrix");
    static_assert(BM % 32 == 0 && BN % 32 == 0, "loader 32-row groups");

    extern __shared__ __align__(16) unsigned char smem_raw[];
    __nv_bfloat16 (*As)[72] = reinterpret_cast<__nv_bfloat16 (*)[72]>(smem_raw);
    __nv_bfloat16 (*Bs)[72] =
        reinterpret_cast<__nv_bfloat16 (*)[72]>(smem_raw + (size_t)S * BM * 72 * 2);

    const int tid  = threadIdx.x;
    const int warp = tid >> 5, lane = tid & 31;
    const int g = lane >> 2, t = lane & 3;
    const int wm = (warp % WM) * (MT * 16);
    const int wn = (warp / WM) * (NT * 8);
    const int bm0 = blockIdx.y * BM;
    const int bn0 = blockIdx.x * BN;

    const int a_row = wm + (lane & 15);
    const int a_col = (lane >> 4) << 3;
    const int b_row = wn + (lane & 7) + ((lane >> 4) << 3);
    const int b_col = ((lane >> 3) & 1) << 3;

    float acc[MT][NT][4];
#pragma unroll
    for (int i = 0; i < MT; i++)
#pragma unroll
        for (int j = 0; j < NT; j++)
#pragma unroll
            for (int c = 0; c < 4; c++) acc[i][j][c] = 0.0f;

    // loader: 64 bf16 per row = 8 x 16B chunks; 8 threads per row
    const int r_  = tid >> 3;          // 0..31
    const int kp_ = (tid & 7) * 8;     // 0..56

    auto load_stage = [&](int s, int k0) {
#pragma unroll
        for (int r = r_; r < BM; r += 32)
            CP16(smem_u32(&As[s * BM + r][kp_]),
                 &A[(size_t)(bm0 + r) * K + k0 + kp_]);
#pragma unroll
        for (int r = r_; r < BN; r += 32)
            CP16(smem_u32(&Bs[s * BN + r][kp_]),
                 &Bt[(size_t)(bn0 + r) * K + k0 + kp_]);
        CP_COMMIT();
    };

    const int niter = K >> 6;          // BK = 64
    load_stage(0, 0);
    if (niter > 1) load_stage(1, 64);

    for (int it = 0; it < niter; it++) {
        const int buf = it % S;
        if (it + 1 < niter) asm volatile("cp.async.wait_group 1;\n");
        else                asm volatile("cp.async.wait_group 0;\n");
        __syncthreads();

        if (it + 2 < niter) load_stage((it + 2) % S, (it + 2) << 6);

#pragma unroll
        for (int ks = 0; ks < 64; ks += 16) {
            uint32_t af[MT][4], bf[NT][2];
#pragma unroll
            for (int mt = 0; mt < MT; mt++)
                ldsm_x4(af[mt][0], af[mt][1], af[mt][2], af[mt][3],
                        smem_u32(&As[buf * BM + a_row + mt * 16][a_col + ks]));
#pragma unroll
            for (int p = 0; p < NT / 2; p++)
                ldsm_x4(bf[2 * p][0], bf[2 * p][1], bf[2 * p + 1][0], bf[2 * p + 1][1],
                        smem_u32(&Bs[buf * BN + b_row + p * 16][b_col + ks]));
#pragma unroll
            for (int mt = 0; mt < MT; mt++)
#pragma unroll
                for (int nt = 0; nt < NT; nt++) {
                    asm volatile(
                        "mma.sync.aligned.m16n8k16.row.col.f32.bf16.bf16.f32 "
                        "{%0,%1,%2,%3}, {%4,%5,%6,%7}, {%8,%9}, {%0,%1,%2,%3};\n"
                        : "+f"(acc[mt][nt][0]), "+f"(acc[mt][nt][1]),
                          "+f"(acc[mt][nt][2]), "+f"(acc[mt][nt][3])
                        : "r"(af[mt][0]), "r"(af[mt][1]), "r"(af[mt][2]), "r"(af[mt][3]),
                          "r"(bf[nt][0]), "r"(bf[nt][1]));
                }
        }
    }

#pragma unroll
    for (int mt = 0; mt < MT; mt++) {
        int row0 = bm0 + wm + mt * 16 + g;
#pragma unroll
        for (int nt = 0; nt < NT; nt++) {
            int col = bn0 + wn + nt * 8 + 2 * t;
            float b0v = bias[col], b1v = bias[col + 1];
            float v00 = fmaxf(acc[mt][nt][0] + b0v, 0.0f);
            float v01 = fmaxf(acc[mt][nt][1] + b1v, 0.0f);
            float v10 = fmaxf(acc[mt][nt][2] + b0v, 0.0f);
            float v11 = fmaxf(acc[mt][nt][3] + b1v, 0.0f);
            __nv_bfloat162 p0 = __floats2bfloat162_rn(v00, v01);
            __nv_bfloat162 p1 = __floats2bfloat162_rn(v10, v11);
            *(__nv_bfloat162*)&C[(size_t)row0 * N + col]       = p0;
            *(__nv_bfloat162*)&C[(size_t)(row0 + 8) * N + col] = p1;
        }
    }
}

// ---------------------------------------------------------------------------
// Head: cross recurrence + h3 dot + sigmoid. One warp per row, 8 rows/block.
// ---------------------------------------------------------------------------
__global__ __launch_bounds__(256) void k_head(
    const __nv_bfloat16* __restrict__ h3,
    const float* __restrict__ out_w,
    const float* __restrict__ out_b,
    float* __restrict__ out)
{
    const int b = blockIdx.x * 8 + (threadIdx.x >> 5);
    const int l = threadIdx.x & 31;
    float p = 0.0f;
#pragma unroll
    for (int j = 0; j < N3 / 32; j++) {
        int idx = l + j * 32;
        p += __bfloat162float(h3[b * N3 + idx]) * out_w[D_ + idx];
    }
#pragma unroll
    for (int o = 16; o > 0; o >>= 1) p += __shfl_xor_sync(0xffffffffu, p, o);
    if (l == 0) {
        float4 rr = *(const float4*)&g_qrow[b * 4];
        float t1 = g_tconst[0], t2 = g_tconst[1], u = g_tconst[2];
        float a1 = 1.0f + rr.x;
        float s1 = a1 * rr.y + t1;
        float a2 = a1 + s1;
        float s2 = a2 * rr.z + t2;
        float a3 = a2 + s2;
        float xdot = a3 * rr.w + u;
        float logit = xdot + p + out_b[0];
        out[b] = 1.0f / (1.0f + expf(-logit));
    }
}

// ---------------------------------------------------------------------------
extern "C" void kernel_launch(void* const* d_in, const int* in_sizes, int n_in,
                              void* d_out, int out_size)
{
    const int*   ids     = (const int*)  d_in[0];
    const float* emb     = (const float*)d_in[1];
    const float* cross_w = (const float*)d_in[2];
    const float* cross_b = (const float*)d_in[3];
    const float* w1      = (const float*)d_in[4];
    const float* b1      = (const float*)d_in[5];
    const float* w2      = (const float*)d_in[6];
    const float* b2      = (const float*)d_in[7];
    const float* w3      = (const float*)d_in[8];
    const float* b3      = (const float*)d_in[9];
    const float* out_w   = (const float*)d_in[10];
    const float* out_b   = (const float*)d_in[11];
    float* out = (float*)d_out;

    __nv_bfloat16 *x0b, *h1b, *h2b, *h3b, *w1t, *w2t, *w3t;
    cudaGetSymbolAddress((void**)&x0b, g_x0b);
    cudaGetSymbolAddress((void**)&h1b, g_h1b);
    cudaGetSymbolAddress((void**)&h2b, g_h2b);
    cudaGetSymbolAddress((void**)&h3b, g_h3b);
    cudaGetSymbolAddress((void**)&w1t, g_w1t);
    cudaGetSymbolAddress((void**)&w2t, g_w2t);
    cudaGetSymbolAddress((void**)&w3t, g_w3t);

    // dynamic smem: 3 * (BM+BN) * 72 * 2 bytes
    const int smem1 = 3 * (128 + 128) * 72 * 2;   // 110592
    const int smem2 = 3 * (128 +  64) * 72 * 2;   // 82944
    const int smem3 = 3 * ( 64 +  64) * 72 * 2;   // 55296
    cudaFuncSetAttribute((const void*)k_gemm_bf16<2, 4, 4, 4>,
                         cudaFuncAttributeMaxDynamicSharedMemorySize, smem1);
    cudaFuncSetAttribute((const void*)k_gemm_bf16<4, 2, 2, 4>,
                         cudaFuncAttributeMaxDynamicSharedMemorySize, smem2);
    cudaFuncSetAttribute((const void*)k_gemm_bf16<2, 4, 2, 2>,
                         cudaFuncAttributeMaxDynamicSharedMemorySize, smem3);

    // 0+1) gather + all prep fused into ONE launch (gather blocks first)
    k_front<<<FRONT_BLOCKS, 256>>>(ids, emb, cross_w, cross_b, out_w,
                                   w1, w2, w3, w1t, w2t, w3t);

    // 2) deep tower — round-14 (103.1us) tiles/grids, BK=64 slabs
    k_gemm_bf16<2, 4, 4, 4><<<dim3(N1 / 128, B_ / 128), 256, smem1>>>(x0b, w1t, b1, h1b, B_, N1, D_);
    k_gemm_bf16<4, 2, 2, 4><<<dim3(N2 /  64, B_ / 128), 256, smem2>>>(h1b, w2t, b2, h2b, B_, N2, N1);
    k_gemm_bf16<2, 4, 2, 2><<<dim3(N3 /  64, B_ /  64), 256, smem3>>>(h2b, w3t, b3, h3b, B_, N3, N2);

    // 3) head (includes cross recurrence)
    k_head<<<B_ / 8, 256>>>(h3b, out_w, out_b, out);
}